// round 10
// baseline (speedup 1.0000x reference)
#include <cuda_runtime.h>
#include <math.h>

typedef unsigned long long u64;

// ---------------- scratch (device globals; no allocation allowed) ----------
__device__ float g_s1[128 * 20 * 24 * 24];   // adder1 out [B,20,24,24]
__device__ float g_s2[128 * 50 * 8 * 8];     // adder2 out [B,50,8,8]
__device__ float g_h[128 * 500];             // fc1 activations
__device__ __align__(16) u64 g_w2pd[50 * 20 * 5 * 8];  // w2 dup pairs [oc][c][kh][8]

__device__ float g_bsum1[20 * 128], g_bsq1[20 * 128];
__device__ float g_bsum2[50 * 128], g_bsq2[50 * 128];

__device__ u64 g_barctr = 0;  // monotonic epoch barrier counter

// grid-wide barrier: monotonic counter, safe across graph replays
__device__ __forceinline__ void grid_barrier() {
    __syncthreads();
    if (threadIdx.x == 0) {
        __threadfence();
        u64 old = atomicAdd(&g_barctr, 1ULL);
        u64 target = (old / gridDim.x + 1ULL) * (u64)gridDim.x;
        while (*((volatile u64*)&g_barctr) < target) { }
        __threadfence();
    }
    __syncthreads();
}

// packed f32x2 fma
__device__ __forceinline__ u64 f32x2_fma(u64 a, u64 b, u64 c) {
    u64 d;
    asm("fma.rn.f32x2 %0, %1, %2, %3;" : "=l"(d) : "l"(a), "l"(b), "l"(c));
    return d;
}

#define NEG1_X2 0xBF800000BF800000ULL
#define ABS_MASK 0x7FFFFFFF7FFFFFFFULL

// ---------------- shared memory union over stages ---------------------------
struct SA { float xs[784]; float ws[500]; float red_s[960]; float red_q[960]; };
struct SB { float xs[2880]; float red_s[800]; float red_q[800]; float s1s[20]; float s1b[20]; };
struct SC { float p_s[4][800]; float s2s[50]; float s2b[50]; };
struct SD { float logits[10]; };
union SU { SA a; SB b; SC c; SD d; };

// ---------------- mega kernel ----------------------------------------------
__global__ __launch_bounds__(1024, 1) void mega_k(
    const float* __restrict__ x,      const float* __restrict__ w1,
    const float* __restrict__ gamma1, const float* __restrict__ beta1,
    const float* __restrict__ w2,
    const float* __restrict__ gamma2, const float* __restrict__ beta2,
    const float* __restrict__ fc1_w,  const float* __restrict__ fc1_b,
    const float* __restrict__ fc2_w,  const float* __restrict__ fc2_b,
    float* __restrict__ out)
{
    __shared__ __align__(16) SU sm;

    const int blk  = blockIdx.x;        // 0..127
    const int tid  = threadIdx.x;
    const int wid  = tid / 32;
    const int lane = tid % 32;

    // ======================= STAGE A: adder1 (+ w2 pair-repack) ============
    {
        const int b = blk;
        // w2 repack slice: 128 blocks x 196 >= 25000; store (w,w) pairs
        {
            const int i = b * 196 + tid;
            if (tid < 196 && i < 25000) {
                const int oc = i / 500;
                const int r  = i % 500;
                const int c  = r / 25;
                const int k  = r % 25;
                const int kh = k / 5;
                const int kw = k % 5;
                unsigned int bits = __float_as_uint(w2[i]);
                g_w2pd[(((oc * 20 + c) * 5 + kh) * 8) + kw] = ((u64)bits << 32) | (u64)bits;
            }
        }
        for (int i = tid; i < 784; i += 1024) sm.a.xs[i] = x[b * 784 + i];
        for (int i = tid; i < 500; i += 1024) sm.a.ws[i] = w1[i];
        __syncthreads();

        if (tid < 960) {
            const int oc   = tid / 48;
            const int r    = tid % 48;
            const int ph   = r / 2;
            const int half = r % 2;

            float acc[12];
#pragma unroll
            for (int p = 0; p < 12; p++) acc[p] = 0.f;

#pragma unroll
            for (int kh = 0; kh < 5; kh++) {
                const float4* xrow = (const float4*)(sm.a.xs + (ph + kh) * 28 + half * 12);
                float xr[16];
                float4 v0 = xrow[0], v1 = xrow[1], v2 = xrow[2], v3 = xrow[3];
                xr[0]=v0.x; xr[1]=v0.y; xr[2]=v0.z; xr[3]=v0.w;
                xr[4]=v1.x; xr[5]=v1.y; xr[6]=v1.z; xr[7]=v1.w;
                xr[8]=v2.x; xr[9]=v2.y; xr[10]=v2.z; xr[11]=v2.w;
                xr[12]=v3.x; xr[13]=v3.y; xr[14]=v3.z; xr[15]=v3.w;
#pragma unroll
                for (int kw = 0; kw < 5; kw++) {
                    const float w = sm.a.ws[oc * 25 + kh * 5 + kw];
#pragma unroll
                    for (int p = 0; p < 12; p++) {
                        float d = fmaf(w, -1.0f, xr[p + kw]);
                        acc[p]  = fmaf(fabsf(d), -1.0f, acc[p]);
                    }
                }
            }

            float lsum = 0.f, lsq = 0.f;
            float* outp = g_s1 + ((b * 20 + oc) * 24 + ph) * 24 + half * 12;
#pragma unroll
            for (int p = 0; p < 12; p++) {
                outp[p] = acc[p];
                lsum += acc[p];
                lsq  += acc[p] * acc[p];
            }
            sm.a.red_s[tid] = lsum;
            sm.a.red_q[tid] = lsq;
        }
        __syncthreads();

        if (tid < 960 && (tid % 48) == 0) {   // 20 threads, deterministic
            const int oc = tid / 48;
            float s = 0.f, q = 0.f;
            for (int t = 0; t < 48; t++) { s += sm.a.red_s[oc * 48 + t]; q += sm.a.red_q[oc * 48 + t]; }
            g_bsum1[oc * 128 + b] = s;
            g_bsq1[oc * 128 + b]  = q;
        }
    }

    grid_barrier();

    // ======================= STAGE B: bn1+pool + adder2 (f32x2 packed) =====
    {
        const int b = blk;

        // bnparam1: warp per channel (redundant per block, deterministic)
        if (wid < 20) {
            float s = 0.f, q = 0.f;
#pragma unroll
            for (int i = 0; i < 4; i++) {
                const int bb = lane + 32 * i;
                s += g_bsum1[wid * 128 + bb];
                q += g_bsq1[wid * 128 + bb];
            }
#pragma unroll
            for (int d = 16; d; d >>= 1) {
                s += __shfl_xor_sync(0xffffffffu, s, d);
                q += __shfl_xor_sync(0xffffffffu, q, d);
            }
            if (lane == 0) {
                const float invN = 1.f / (128.f * 24.f * 24.f);
                float m = s * invN;
                float v = q * invN - m * m;
                float sc = gamma1[wid] * rsqrtf(v + 1e-5f);
                sm.b.s1s[wid] = sc;
                sm.b.s1b[wid] = beta1[wid] - m * sc;
            }
        }
        __syncthreads();

        for (int i = tid; i < 2880; i += 1024) {
            const int c   = i / 144;
            const int rem = i % 144;
            const int ph2 = rem / 12;
            const int pw2 = rem % 12;
            const float* base = g_s1 + ((b * 20 + c) * 24 + ph2 * 2) * 24 + pw2 * 2;
            const float s = sm.b.s1s[c], be = sm.b.s1b[c];
            float a0 = base[0]  * s + be;
            float a1 = base[1]  * s + be;
            float a2 = base[24] * s + be;
            float a3 = base[25] * s + be;
            sm.b.xs[i] = fmaxf(fmaxf(a0, a1), fmaxf(a2, a3));
        }
        __syncthreads();

        if (tid < 800) {
            const int oc   = tid / 16;
            const int sub  = tid % 16;
            const int ph   = sub / 2;
            const int half = sub % 2;     // pw block: half*4 .. half*4+3

            u64 a01 = 0ULL, a23 = 0ULL;   // packed accumulators (p0,p1),(p2,p3)

            for (int c = 0; c < 20; c++) {
                const float* xc = sm.b.xs + c * 144 + half * 4;
                const u64* wbase = g_w2pd + ((oc * 20 + c) * 5) * 8;
#pragma unroll
                for (int kh = 0; kh < 5; kh++) {
                    // x window: 8 floats = 2 x LDS.128, halves are even pairs
                    const ulonglong2* xrow = (const ulonglong2*)(xc + (ph + kh) * 12);
                    ulonglong2 va = xrow[0], vb = xrow[1];
                    u64 e0 = va.x, e1 = va.y, e2 = vb.x, e3 = vb.y;
                    u64 o0 = (e0 >> 32) | (e1 << 32);
                    u64 o1 = (e1 >> 32) | (e2 << 32);
                    u64 o2 = (e2 >> 32) | (e3 << 32);

                    const u64* wp = wbase + kh * 8;
                    ulonglong2 wA = *(const ulonglong2*)wp;
                    ulonglong2 wB = *((const ulonglong2*)wp + 1);
                    u64 w0 = wA.x, w1v = wA.y, w2v = wB.x, w3v = wB.y;
                    u64 w4v = wp[4];

#define PSTEP(accv, xp, wv) { u64 d_ = f32x2_fma((wv), NEG1_X2, (xp)); d_ &= ABS_MASK; \
                              (accv) = f32x2_fma(d_, NEG1_X2, (accv)); }
                    PSTEP(a01, e0, w0);  PSTEP(a23, e1, w0);   // kw=0
                    PSTEP(a01, o0, w1v); PSTEP(a23, o1, w1v);  // kw=1
                    PSTEP(a01, e1, w2v); PSTEP(a23, e2, w2v);  // kw=2
                    PSTEP(a01, o1, w3v); PSTEP(a23, o2, w3v);  // kw=3
                    PSTEP(a01, e2, w4v); PSTEP(a23, e3, w4v);  // kw=4
#undef PSTEP
                }
            }

            float acc[4];
            acc[0] = __uint_as_float((unsigned int)(a01 & 0xFFFFFFFFULL));
            acc[1] = __uint_as_float((unsigned int)(a01 >> 32));
            acc[2] = __uint_as_float((unsigned int)(a23 & 0xFFFFFFFFULL));
            acc[3] = __uint_as_float((unsigned int)(a23 >> 32));

            float lsum = 0.f, lsq = 0.f;
            float* op = g_s2 + ((b * 50 + oc) * 8 + ph) * 8 + half * 4;
#pragma unroll
            for (int p = 0; p < 4; p++) {
                op[p] = acc[p];
                lsum += acc[p];
                lsq  += acc[p] * acc[p];
            }
            sm.b.red_s[tid] = lsum;
            sm.b.red_q[tid] = lsq;
        }
        __syncthreads();

        if (tid < 800 && (tid % 16) == 0) {   // 50 threads, deterministic
            const int oc = tid / 16;
            float s = 0.f, q = 0.f;
            for (int t = 0; t < 16; t++) { s += sm.b.red_s[oc * 16 + t]; q += sm.b.red_q[oc * 16 + t]; }
            g_bsum2[oc * 128 + b] = s;
            g_bsq2[oc * 128 + b]  = q;
        }
    }

    grid_barrier();

    // ======================= STAGE C: bn2+pool + fc1 ========================
    {
        const int bg = blk >> 2;
        const int oq = blk & 3;
        const int b0 = bg * 4;

        // bnparam2: 32 warps cover 50 channels (redundant per block)
        for (int c = wid; c < 50; c += 32) {
            float s = 0.f, q = 0.f;
#pragma unroll
            for (int i = 0; i < 4; i++) {
                const int bb = lane + 32 * i;
                s += g_bsum2[c * 128 + bb];
                q += g_bsq2[c * 128 + bb];
            }
#pragma unroll
            for (int d = 16; d; d >>= 1) {
                s += __shfl_xor_sync(0xffffffffu, s, d);
                q += __shfl_xor_sync(0xffffffffu, q, d);
            }
            if (lane == 0) {
                const float invN = 1.f / (128.f * 8.f * 8.f);
                float m = s * invN;
                float v = q * invN - m * m;
                float sc = gamma2[c] * rsqrtf(v + 1e-5f);
                sm.c.s2s[c] = sc;
                sm.c.s2b[c] = beta2[c] - m * sc;
            }
        }
        __syncthreads();

        for (int i = tid; i < 3200; i += 1024) {
            const int bb = i / 800;
            const int o  = i % 800;
            const int c   = o / 16;
            const int r   = (o % 16) / 4;
            const int col = o % 4;
            const float* base = g_s2 + (((b0 + bb) * 50 + c) * 8 + r * 2) * 8 + col * 2;
            const float s = sm.c.s2s[c], be = sm.c.s2b[c];
            float a0 = base[0] * s + be;
            float a1 = base[1] * s + be;
            float a2 = base[8] * s + be;
            float a3 = base[9] * s + be;
            sm.c.p_s[bb][o] = fmaxf(fmaxf(a0, a1), fmaxf(a2, a3));
        }
        __syncthreads();

        // 32 warps x 4 outputs x 4 batches
        int olist[4];
        const float4* wrow[4];
#pragma unroll
        for (int j = 0; j < 4; j++) {
            int idx = wid * 4 + j;
            bool valid = idx < 125;
            int o = oq * 125 + (valid ? idx : 0);
            olist[j] = valid ? o : -1;
            wrow[j] = (const float4*)(fc1_w + o * 800);
        }

        float acc[4][4];
#pragma unroll
        for (int j = 0; j < 4; j++)
#pragma unroll
            for (int bb = 0; bb < 4; bb++) acc[j][bb] = 0.f;

#pragma unroll
        for (int i = 0; i < 7; i++) {
            const int fidx = lane + 32 * i;
            const bool v = fidx < 200;
            float4 x4[4];
#pragma unroll
            for (int bb = 0; bb < 4; bb++)
                x4[bb] = v ? ((const float4*)sm.c.p_s[bb])[fidx] : make_float4(0.f,0.f,0.f,0.f);
#pragma unroll
            for (int j = 0; j < 4; j++) {
                float4 wv = v ? wrow[j][fidx] : make_float4(0.f,0.f,0.f,0.f);
#pragma unroll
                for (int bb = 0; bb < 4; bb++) {
                    acc[j][bb] = fmaf(wv.x, x4[bb].x, acc[j][bb]);
                    acc[j][bb] = fmaf(wv.y, x4[bb].y, acc[j][bb]);
                    acc[j][bb] = fmaf(wv.z, x4[bb].z, acc[j][bb]);
                    acc[j][bb] = fmaf(wv.w, x4[bb].w, acc[j][bb]);
                }
            }
        }

#pragma unroll
        for (int j = 0; j < 4; j++) {
#pragma unroll
            for (int bb = 0; bb < 4; bb++) {
                float a = acc[j][bb];
#pragma unroll
                for (int d = 16; d; d >>= 1) a += __shfl_xor_sync(0xffffffffu, a, d);
                acc[j][bb] = a;
            }
            if (lane == 0 && olist[j] >= 0) {
                const float bia = fc1_b[olist[j]];
#pragma unroll
                for (int bb = 0; bb < 4; bb++)
                    g_h[(b0 + bb) * 500 + olist[j]] = fmaxf(acc[j][bb] + bia, 0.f);
            }
        }
    }

    grid_barrier();

    // ======================= STAGE D: fc2 + softmax =========================
    {
        const int b = blk;
        if (tid < 320) {
            float a = 0.f;
            const float* wr = fc2_w + wid * 500;
            const float* hr = g_h + b * 500;
#pragma unroll
            for (int i = 0; i < 16; i++) {
                int k = lane + 32 * i;
                if (k < 500) a = fmaf(wr[k], hr[k], a);
            }
#pragma unroll
            for (int d = 16; d; d >>= 1) a += __shfl_xor_sync(0xffffffffu, a, d);
            if (lane == 0) sm.d.logits[wid] = a + fc2_b[wid];
        }
        __syncthreads();

        if (tid < 10) {
            const int j = tid;
            float mx = -1e30f;
            for (int t = 0; t < 10; t++) mx = fmaxf(mx, sm.d.logits[t]);
            float sum = 0.f;
            for (int t = 0; t < 10; t++) sum += expf(sm.d.logits[t] - mx);
            out[b * 10 + j] = expf(sm.d.logits[j] - mx) / sum;
        }
    }
}

// ---------------- launch ----------------------------------------------------
extern "C" void kernel_launch(void* const* d_in, const int* in_sizes, int n_in,
                              void* d_out, int out_size) {
    const float* x      = (const float*)d_in[0];
    const float* w1     = (const float*)d_in[1];
    const float* gamma1 = (const float*)d_in[2];
    const float* beta1  = (const float*)d_in[3];
    const float* w2     = (const float*)d_in[4];
    const float* gamma2 = (const float*)d_in[5];
    const float* beta2  = (const float*)d_in[6];
    const float* fc1_w  = (const float*)d_in[7];
    const float* fc1_b  = (const float*)d_in[8];
    const float* fc2_w  = (const float*)d_in[9];
    const float* fc2_b  = (const float*)d_in[10];
    float* out = (float*)d_out;

    mega_k<<<128, 1024>>>(x, w1, gamma1, beta1, w2, gamma2, beta2,
                          fc1_w, fc1_b, fc2_w, fc2_b, out);
}

// round 11
// speedup vs baseline: 1.1812x; 1.1812x over previous
#include <cuda_runtime.h>
#include <math.h>

typedef unsigned long long u64;

// ---------------- scratch (device globals; no allocation allowed) ----------
__device__ float g_s1[128 * 20 * 24 * 24];   // adder1 out [B,20,24,24]
__device__ float g_s2[128 * 50 * 8 * 8];     // adder2 out [B,50,8,8]
__device__ float g_h[128 * 500];             // fc1 activations
__device__ __align__(16) float g_w2p[50 * 20 * 28];  // padded w2 [oc][c][28]

__device__ float g_bsum1[20 * 128], g_bsq1[20 * 128];
__device__ float g_bsum2[50 * 128], g_bsq2[50 * 128];

__device__ u64 g_barctr = 0;  // monotonic epoch barrier counter

// grid-wide barrier: monotonic counter, safe across graph replays
__device__ __forceinline__ void grid_barrier() {
    __syncthreads();
    if (threadIdx.x == 0) {
        __threadfence();
        u64 old = atomicAdd(&g_barctr, 1ULL);
        u64 target = (old / gridDim.x + 1ULL) * (u64)gridDim.x;
        while (*((volatile u64*)&g_barctr) < target) { }
        __threadfence();
    }
    __syncthreads();
}

// ---------------- shared memory union over stages ---------------------------
struct SA { float xs[784]; float ws[500]; float red_s[960]; float red_q[960]; };
struct SB { float xs[2880]; float part[2][3200]; float red_s[400]; float red_q[400];
            float s1s[20]; float s1b[20]; };
struct SC { float p_s[4][800]; float s2s[50]; float s2b[50]; };
struct SD { float logits[10]; };
union SU { SA a; SB b; SC c; SD d; };

// ---------------- mega kernel ----------------------------------------------
__global__ __launch_bounds__(1024, 1) void mega_k(
    const float* __restrict__ x,      const float* __restrict__ w1,
    const float* __restrict__ gamma1, const float* __restrict__ beta1,
    const float* __restrict__ w2,
    const float* __restrict__ gamma2, const float* __restrict__ beta2,
    const float* __restrict__ fc1_w,  const float* __restrict__ fc1_b,
    const float* __restrict__ fc2_w,  const float* __restrict__ fc2_b,
    float* __restrict__ out)
{
    __shared__ __align__(16) SU sm;

    const int blk  = blockIdx.x;        // 0..127
    const int tid  = threadIdx.x;
    const int wid  = tid / 32;
    const int lane = tid % 32;

    // ======================= STAGE A: adder1 (+ w2 repack) =================
    {
        const int b = blk;
        // w2 repack slice: 128 blocks x 196 >= 25000
        {
            const int i = b * 196 + tid;
            if (tid < 196 && i < 25000) {
                const int oc = i / 500;
                const int r  = i % 500;
                g_w2p[oc * 560 + (r / 25) * 28 + (r % 25)] = w2[i];
            }
        }
        for (int i = tid; i < 784; i += 1024) sm.a.xs[i] = x[b * 784 + i];
        for (int i = tid; i < 500; i += 1024) sm.a.ws[i] = w1[i];
        __syncthreads();

        if (tid < 960) {
            const int oc   = tid / 48;
            const int r    = tid % 48;
            const int ph   = r / 2;
            const int half = r % 2;

            float acc[12];
#pragma unroll
            for (int p = 0; p < 12; p++) acc[p] = 0.f;

#pragma unroll
            for (int kh = 0; kh < 5; kh++) {
                const float4* xrow = (const float4*)(sm.a.xs + (ph + kh) * 28 + half * 12);
                float xr[16];
                float4 v0 = xrow[0], v1 = xrow[1], v2 = xrow[2], v3 = xrow[3];
                xr[0]=v0.x; xr[1]=v0.y; xr[2]=v0.z; xr[3]=v0.w;
                xr[4]=v1.x; xr[5]=v1.y; xr[6]=v1.z; xr[7]=v1.w;
                xr[8]=v2.x; xr[9]=v2.y; xr[10]=v2.z; xr[11]=v2.w;
                xr[12]=v3.x; xr[13]=v3.y; xr[14]=v3.z; xr[15]=v3.w;
#pragma unroll
                for (int kw = 0; kw < 5; kw++) {
                    const float w = sm.a.ws[oc * 25 + kh * 5 + kw];
#pragma unroll
                    for (int p = 0; p < 12; p++) {
                        float d = fmaf(w, -1.0f, xr[p + kw]);          // FFMA-imm rt1
                        acc[p]  = fmaf(fabsf(d), -1.0f, acc[p]);       // FFMA-imm rt1
                    }
                }
            }

            float lsum = 0.f, lsq = 0.f;
            float* outp = g_s1 + ((b * 20 + oc) * 24 + ph) * 24 + half * 12;
#pragma unroll
            for (int p = 0; p < 12; p++) {
                outp[p] = acc[p];
                lsum += acc[p];
                lsq  += acc[p] * acc[p];
            }
            sm.a.red_s[tid] = lsum;
            sm.a.red_q[tid] = lsq;
        }
        __syncthreads();

        if (tid < 960 && (tid % 48) == 0) {   // 20 threads, deterministic
            const int oc = tid / 48;
            float s = 0.f, q = 0.f;
            for (int t = 0; t < 48; t++) { s += sm.a.red_s[oc * 48 + t]; q += sm.a.red_q[oc * 48 + t]; }
            g_bsum1[oc * 128 + b] = s;
            g_bsq1[oc * 128 + b]  = q;
        }
    }

    grid_barrier();

    // ======================= STAGE B: bn1+pool + adder2 =====================
    // thread = (oc 0..49, ph 0..7, chalf 0..1): full 8-wide row, 10 channels
    {
        const int b = blk;

        // bnparam1: warp per channel (redundant per block, deterministic)
        if (wid < 20) {
            float s = 0.f, q = 0.f;
#pragma unroll
            for (int i = 0; i < 4; i++) {
                const int bb = lane + 32 * i;
                s += g_bsum1[wid * 128 + bb];
                q += g_bsq1[wid * 128 + bb];
            }
#pragma unroll
            for (int d = 16; d; d >>= 1) {
                s += __shfl_xor_sync(0xffffffffu, s, d);
                q += __shfl_xor_sync(0xffffffffu, q, d);
            }
            if (lane == 0) {
                const float invN = 1.f / (128.f * 24.f * 24.f);
                float m = s * invN;
                float v = q * invN - m * m;
                float sc = gamma1[wid] * rsqrtf(v + 1e-5f);
                sm.b.s1s[wid] = sc;
                sm.b.s1b[wid] = beta1[wid] - m * sc;
            }
        }
        __syncthreads();

        for (int i = tid; i < 2880; i += 1024) {
            const int c   = i / 144;
            const int rem = i % 144;
            const int ph2 = rem / 12;
            const int pw2 = rem % 12;
            const float* base = g_s1 + ((b * 20 + c) * 24 + ph2 * 2) * 24 + pw2 * 2;
            const float s = sm.b.s1s[c], be = sm.b.s1b[c];
            float a0 = base[0]  * s + be;
            float a1 = base[1]  * s + be;
            float a2 = base[24] * s + be;
            float a3 = base[25] * s + be;
            sm.b.xs[i] = fmaxf(fmaxf(a0, a1), fmaxf(a2, a3));
        }
        __syncthreads();

        if (tid < 800) {
            const int oc  = tid / 16;
            const int sub = tid % 16;
            const int ph  = sub >> 1;
            const int ch  = sub & 1;          // c range: ch*10 .. ch*10+9

            float acc[8];
#pragma unroll
            for (int p = 0; p < 8; p++) acc[p] = 0.f;

            const float4* wbase = (const float4*)(g_w2p + oc * 560);

            for (int cc = 0; cc < 10; cc++) {
                const int c = ch * 10 + cc;
                float wv[28];
                const float4* wp4 = wbase + c * 7;
#pragma unroll
                for (int q = 0; q < 7; q++) {
                    float4 t = wp4[q];
                    wv[q*4+0] = t.x; wv[q*4+1] = t.y; wv[q*4+2] = t.z; wv[q*4+3] = t.w;
                }
                const float* xc = sm.b.xs + c * 144;
#pragma unroll
                for (int kh = 0; kh < 5; kh++) {
                    const float4* xrow = (const float4*)(xc + (ph + kh) * 12);
                    float4 v0 = xrow[0], v1 = xrow[1], v2 = xrow[2];
                    float xr[12];
                    xr[0]=v0.x; xr[1]=v0.y; xr[2]=v0.z; xr[3]=v0.w;
                    xr[4]=v1.x; xr[5]=v1.y; xr[6]=v1.z; xr[7]=v1.w;
                    xr[8]=v2.x; xr[9]=v2.y; xr[10]=v2.z; xr[11]=v2.w;
#pragma unroll
                    for (int kw = 0; kw < 5; kw++) {
                        const float w = wv[kh * 5 + kw];
#pragma unroll
                        for (int p = 0; p < 8; p++) {
                            float d = fmaf(w, -1.0f, xr[p + kw]);       // FFMA-imm
                            acc[p]  = fmaf(fabsf(d), -1.0f, acc[p]);    // FFMA-imm
                        }
                    }
                }
            }

            float* pp = &sm.b.part[ch][oc * 64 + ph * 8];
#pragma unroll
            for (int p = 0; p < 8; p++) pp[p] = acc[p];
        }
        __syncthreads();

        // combine c-halves (deterministic left-to-right), write out + partials
        if (tid < 400) {
            const int oc = tid / 8;
            const int ph = tid % 8;
            const float* p0 = &sm.b.part[0][oc * 64 + ph * 8];
            const float* p1 = &sm.b.part[1][oc * 64 + ph * 8];
            float* op = g_s2 + ((b * 50 + oc) * 8 + ph) * 8;
            float lsum = 0.f, lsq = 0.f;
#pragma unroll
            for (int p = 0; p < 8; p++) {
                float v = p0[p] + p1[p];
                op[p] = v;
                lsum += v;
                lsq  += v * v;
            }
            sm.b.red_s[tid] = lsum;
            sm.b.red_q[tid] = lsq;
        }
        __syncthreads();

        if (tid < 50) {   // per-oc reduce over 8 ph rows (deterministic)
            float s = 0.f, q = 0.f;
            for (int t = 0; t < 8; t++) { s += sm.b.red_s[tid * 8 + t]; q += sm.b.red_q[tid * 8 + t]; }
            g_bsum2[tid * 128 + b] = s;
            g_bsq2[tid * 128 + b]  = q;
        }
    }

    grid_barrier();

    // ======================= STAGE C: bn2+pool + fc1 ========================
    {
        const int bg = blk >> 2;
        const int oq = blk & 3;
        const int b0 = bg * 4;

        // bnparam2: 32 warps cover 50 channels (redundant per block)
        for (int c = wid; c < 50; c += 32) {
            float s = 0.f, q = 0.f;
#pragma unroll
            for (int i = 0; i < 4; i++) {
                const int bb = lane + 32 * i;
                s += g_bsum2[c * 128 + bb];
                q += g_bsq2[c * 128 + bb];
            }
#pragma unroll
            for (int d = 16; d; d >>= 1) {
                s += __shfl_xor_sync(0xffffffffu, s, d);
                q += __shfl_xor_sync(0xffffffffu, q, d);
            }
            if (lane == 0) {
                const float invN = 1.f / (128.f * 8.f * 8.f);
                float m = s * invN;
                float v = q * invN - m * m;
                float sc = gamma2[c] * rsqrtf(v + 1e-5f);
                sm.c.s2s[c] = sc;
                sm.c.s2b[c] = beta2[c] - m * sc;
            }
        }
        __syncthreads();

        for (int i = tid; i < 3200; i += 1024) {
            const int bb = i / 800;
            const int o  = i % 800;
            const int c   = o / 16;
            const int r   = (o % 16) / 4;
            const int col = o % 4;
            const float* base = g_s2 + (((b0 + bb) * 50 + c) * 8 + r * 2) * 8 + col * 2;
            const float s = sm.c.s2s[c], be = sm.c.s2b[c];
            float a0 = base[0] * s + be;
            float a1 = base[1] * s + be;
            float a2 = base[8] * s + be;
            float a3 = base[9] * s + be;
            sm.c.p_s[bb][o] = fmaxf(fmaxf(a0, a1), fmaxf(a2, a3));
        }
        __syncthreads();

        // 32 warps x 4 outputs x 4 batches
        int olist[4];
        const float4* wrow[4];
#pragma unroll
        for (int j = 0; j < 4; j++) {
            int idx = wid * 4 + j;
            bool valid = idx < 125;
            int o = oq * 125 + (valid ? idx : 0);
            olist[j] = valid ? o : -1;
            wrow[j] = (const float4*)(fc1_w + o * 800);
        }

        float acc[4][4];
#pragma unroll
        for (int j = 0; j < 4; j++)
#pragma unroll
            for (int bb = 0; bb < 4; bb++) acc[j][bb] = 0.f;

#pragma unroll
        for (int i = 0; i < 7; i++) {
            const int fidx = lane + 32 * i;
            const bool v = fidx < 200;
            float4 x4[4];
#pragma unroll
            for (int bb = 0; bb < 4; bb++)
                x4[bb] = v ? ((const float4*)sm.c.p_s[bb])[fidx] : make_float4(0.f,0.f,0.f,0.f);
#pragma unroll
            for (int j = 0; j < 4; j++) {
                float4 wv = v ? wrow[j][fidx] : make_float4(0.f,0.f,0.f,0.f);
#pragma unroll
                for (int bb = 0; bb < 4; bb++) {
                    acc[j][bb] = fmaf(wv.x, x4[bb].x, acc[j][bb]);
                    acc[j][bb] = fmaf(wv.y, x4[bb].y, acc[j][bb]);
                    acc[j][bb] = fmaf(wv.z, x4[bb].z, acc[j][bb]);
                    acc[j][bb] = fmaf(wv.w, x4[bb].w, acc[j][bb]);
                }
            }
        }

#pragma unroll
        for (int j = 0; j < 4; j++) {
#pragma unroll
            for (int bb = 0; bb < 4; bb++) {
                float a = acc[j][bb];
#pragma unroll
                for (int d = 16; d; d >>= 1) a += __shfl_xor_sync(0xffffffffu, a, d);
                acc[j][bb] = a;
            }
            if (lane == 0 && olist[j] >= 0) {
                const float bia = fc1_b[olist[j]];
#pragma unroll
                for (int bb = 0; bb < 4; bb++)
                    g_h[(b0 + bb) * 500 + olist[j]] = fmaxf(acc[j][bb] + bia, 0.f);
            }
        }
    }

    grid_barrier();

    // ======================= STAGE D: fc2 + softmax =========================
    {
        const int b = blk;
        if (tid < 320) {
            float a = 0.f;
            const float* wr = fc2_w + wid * 500;
            const float* hr = g_h + b * 500;
#pragma unroll
            for (int i = 0; i < 16; i++) {
                int k = lane + 32 * i;
                if (k < 500) a = fmaf(wr[k], hr[k], a);
            }
#pragma unroll
            for (int d = 16; d; d >>= 1) a += __shfl_xor_sync(0xffffffffu, a, d);
            if (lane == 0) sm.d.logits[wid] = a + fc2_b[wid];
        }
        __syncthreads();

        if (tid < 10) {
            const int j = tid;
            float mx = -1e30f;
            for (int t = 0; t < 10; t++) mx = fmaxf(mx, sm.d.logits[t]);
            float sum = 0.f;
            for (int t = 0; t < 10; t++) sum += expf(sm.d.logits[t] - mx);
            out[b * 10 + j] = expf(sm.d.logits[j] - mx) / sum;
        }
    }
}

// ---------------- launch ----------------------------------------------------
extern "C" void kernel_launch(void* const* d_in, const int* in_sizes, int n_in,
                              void* d_out, int out_size) {
    const float* x      = (const float*)d_in[0];
    const float* w1     = (const float*)d_in[1];
    const float* gamma1 = (const float*)d_in[2];
    const float* beta1  = (const float*)d_in[3];
    const float* w2     = (const float*)d_in[4];
    const float* gamma2 = (const float*)d_in[5];
    const float* beta2  = (const float*)d_in[6];
    const float* fc1_w  = (const float*)d_in[7];
    const float* fc1_b  = (const float*)d_in[8];
    const float* fc2_w  = (const float*)d_in[9];
    const float* fc2_b  = (const float*)d_in[10];
    float* out = (float*)d_out;

    mega_k<<<128, 1024>>>(x, w1, gamma1, beta1, w2, gamma2, beta2,
                          fc1_w, fc1_b, fc2_w, fc2_b, out);
}

// round 12
// speedup vs baseline: 1.3011x; 1.1015x over previous
#include <cuda_runtime.h>
#include <math.h>

typedef unsigned long long u64;

// ---------------- scratch (device globals; no allocation allowed) ----------
__device__ float g_s1[128 * 20 * 24 * 24];   // adder1 out [B,20,24,24]
__device__ float g_s2[128 * 50 * 8 * 8];     // adder2 out [B,50,8,8]
__device__ float g_h[128 * 500];             // fc1 activations
__device__ __align__(16) float g_w2k[50 * 20 * 5 * 8];  // w2 [oc][c][kh][8] (pad 5->8)

__device__ float g_bsum1[20 * 128], g_bsq1[20 * 128];
__device__ float g_bsum2[50 * 128], g_bsq2[50 * 128];

__device__ u64 g_barctr = 0;  // monotonic epoch barrier counter

// grid-wide barrier: monotonic counter, safe across graph replays
__device__ __forceinline__ void grid_barrier() {
    __syncthreads();
    if (threadIdx.x == 0) {
        __threadfence();
        u64 old = atomicAdd(&g_barctr, 1ULL);
        u64 target = (old / gridDim.x + 1ULL) * (u64)gridDim.x;
        while (*((volatile u64*)&g_barctr) < target) { }
        __threadfence();
    }
    __syncthreads();
}

// ---------------- shared memory union over stages ---------------------------
struct SA { float xs[784]; float ws[500]; float red_s[960]; float red_q[960]; };
struct SB { float xs[2880]; float red_s[200]; float red_q[200]; float s1s[20]; float s1b[20]; };
struct SC { float p_s[4][800]; float s2s[50]; float s2b[50]; };
struct SD { float logits[10]; };
union SU { SA a; SB b; SC c; SD d; };

// ---------------- mega kernel ----------------------------------------------
__global__ __launch_bounds__(1024, 1) void mega_k(
    const float* __restrict__ x,      const float* __restrict__ w1,
    const float* __restrict__ gamma1, const float* __restrict__ beta1,
    const float* __restrict__ w2,
    const float* __restrict__ gamma2, const float* __restrict__ beta2,
    const float* __restrict__ fc1_w,  const float* __restrict__ fc1_b,
    const float* __restrict__ fc2_w,  const float* __restrict__ fc2_b,
    float* __restrict__ out)
{
    __shared__ __align__(16) SU sm;

    const int blk  = blockIdx.x;        // 0..127
    const int tid  = threadIdx.x;
    const int wid  = tid / 32;
    const int lane = tid % 32;

    // ======================= STAGE A: adder1 (+ w2 repack) =================
    {
        const int b = blk;
        // w2 repack slice -> kh-major padded layout: 128 blocks x 196 >= 25000
        {
            const int i = b * 196 + tid;
            if (tid < 196 && i < 25000) {
                const int oc = i / 500;
                const int r  = i % 500;
                const int c  = r / 25;
                const int k  = r % 25;
                g_w2k[(((oc * 20 + c) * 5 + (k / 5)) * 8) + (k % 5)] = w2[i];
            }
        }
        for (int i = tid; i < 784; i += 1024) sm.a.xs[i] = x[b * 784 + i];
        for (int i = tid; i < 500; i += 1024) sm.a.ws[i] = w1[i];
        __syncthreads();

        if (tid < 960) {
            const int oc   = tid / 48;
            const int r    = tid % 48;
            const int ph   = r / 2;
            const int half = r % 2;

            float acc[12];
#pragma unroll
            for (int p = 0; p < 12; p++) acc[p] = 0.f;

#pragma unroll
            for (int kh = 0; kh < 5; kh++) {
                const float4* xrow = (const float4*)(sm.a.xs + (ph + kh) * 28 + half * 12);
                float xr[16];
                float4 v0 = xrow[0], v1 = xrow[1], v2 = xrow[2], v3 = xrow[3];
                xr[0]=v0.x; xr[1]=v0.y; xr[2]=v0.z; xr[3]=v0.w;
                xr[4]=v1.x; xr[5]=v1.y; xr[6]=v1.z; xr[7]=v1.w;
                xr[8]=v2.x; xr[9]=v2.y; xr[10]=v2.z; xr[11]=v2.w;
                xr[12]=v3.x; xr[13]=v3.y; xr[14]=v3.z; xr[15]=v3.w;
#pragma unroll
                for (int kw = 0; kw < 5; kw++) {
                    const float w = sm.a.ws[oc * 25 + kh * 5 + kw];
#pragma unroll
                    for (int p = 0; p < 12; p++) {
                        float d = fmaf(w, -1.0f, xr[p + kw]);          // FFMA-imm rt1
                        acc[p]  = fmaf(fabsf(d), -1.0f, acc[p]);       // FFMA-imm rt1
                    }
                }
            }

            float lsum = 0.f, lsq = 0.f;
            float* outp = g_s1 + ((b * 20 + oc) * 24 + ph) * 24 + half * 12;
#pragma unroll
            for (int p = 0; p < 12; p++) {
                outp[p] = acc[p];
                lsum += acc[p];
                lsq  += acc[p] * acc[p];
            }
            sm.a.red_s[tid] = lsum;
            sm.a.red_q[tid] = lsq;
        }
        __syncthreads();

        if (tid < 960 && (tid % 48) == 0) {   // 20 threads, deterministic
            const int oc = tid / 48;
            float s = 0.f, q = 0.f;
            for (int t = 0; t < 48; t++) { s += sm.a.red_s[oc * 48 + t]; q += sm.a.red_q[oc * 48 + t]; }
            g_bsum1[oc * 128 + b] = s;
            g_bsq1[oc * 128 + b]  = q;
        }
    }

    grid_barrier();

    // ======================= STAGE B: bn1+pool + adder2 =====================
    // thread = (oc 0..49, phpair 0..3, cquarter 0..3): 2 output rows, 5 channels
    {
        const int b = blk;

        // bnparam1: warp per channel (redundant per block, deterministic)
        if (wid < 20) {
            float s = 0.f, q = 0.f;
#pragma unroll
            for (int i = 0; i < 4; i++) {
                const int bb = lane + 32 * i;
                s += g_bsum1[wid * 128 + bb];
                q += g_bsq1[wid * 128 + bb];
            }
#pragma unroll
            for (int d = 16; d; d >>= 1) {
                s += __shfl_xor_sync(0xffffffffu, s, d);
                q += __shfl_xor_sync(0xffffffffu, q, d);
            }
            if (lane == 0) {
                const float invN = 1.f / (128.f * 24.f * 24.f);
                float m = s * invN;
                float v = q * invN - m * m;
                float sc = gamma1[wid] * rsqrtf(v + 1e-5f);
                sm.b.s1s[wid] = sc;
                sm.b.s1b[wid] = beta1[wid] - m * sc;
            }
        }
        __syncthreads();

        for (int i = tid; i < 2880; i += 1024) {
            const int c   = i / 144;
            const int rem = i % 144;
            const int ph2 = rem / 12;
            const int pw2 = rem % 12;
            const float* base = g_s1 + ((b * 20 + c) * 24 + ph2 * 2) * 24 + pw2 * 2;
            const float s = sm.b.s1s[c], be = sm.b.s1b[c];
            float a0 = base[0]  * s + be;
            float a1 = base[1]  * s + be;
            float a2 = base[24] * s + be;
            float a3 = base[25] * s + be;
            sm.b.xs[i] = fmaxf(fmaxf(a0, a1), fmaxf(a2, a3));
        }
        __syncthreads();

        if (tid < 800) {
            const int oc     = tid / 16;
            const int sub    = tid % 16;
            const int phpair = sub >> 2;        // 0..3 -> rows ph0, ph0+1
            const int q      = sub & 3;         // c quarter: q*5 .. q*5+4
            const int ph0    = phpair * 2;

            float acc0[8], acc1[8];
#pragma unroll
            for (int p = 0; p < 8; p++) { acc0[p] = 0.f; acc1[p] = 0.f; }

#pragma unroll
            for (int cc = 0; cc < 5; cc++) {
                const int c = q * 5 + cc;
                const float* xc = sm.b.xs + c * 144 + ph0 * 12;
                const float4* wk = (const float4*)(g_w2k + ((oc * 20 + c) * 5) * 8);

                float wprev[5];
#pragma unroll
                for (int r = 0; r < 6; r++) {
                    float wcur[5];
                    if (r < 5) {
                        float4 wa = wk[r * 2];
                        float4 wb = wk[r * 2 + 1];
                        wcur[0] = wa.x; wcur[1] = wa.y; wcur[2] = wa.z;
                        wcur[3] = wa.w; wcur[4] = wb.x;
                    }
                    const float4* xrow = (const float4*)(xc + r * 12);
                    float4 v0 = xrow[0], v1 = xrow[1], v2 = xrow[2];
                    float xr[12];
                    xr[0]=v0.x; xr[1]=v0.y; xr[2]=v0.z; xr[3]=v0.w;
                    xr[4]=v1.x; xr[5]=v1.y; xr[6]=v1.z; xr[7]=v1.w;
                    xr[8]=v2.x; xr[9]=v2.y; xr[10]=v2.z; xr[11]=v2.w;

                    if (r < 5) {   // row0: kh = r
#pragma unroll
                        for (int kw = 0; kw < 5; kw++) {
                            const float w = wcur[kw];
#pragma unroll
                            for (int p = 0; p < 8; p++) {
                                float d = fmaf(w, -1.0f, xr[p + kw]);
                                acc0[p] = fmaf(fabsf(d), -1.0f, acc0[p]);
                            }
                        }
                    }
                    if (r >= 1) {  // row1: kh = r-1
#pragma unroll
                        for (int kw = 0; kw < 5; kw++) {
                            const float w = wprev[kw];
#pragma unroll
                            for (int p = 0; p < 8; p++) {
                                float d = fmaf(w, -1.0f, xr[p + kw]);
                                acc1[p] = fmaf(fabsf(d), -1.0f, acc1[p]);
                            }
                        }
                    }
#pragma unroll
                    for (int k = 0; k < 5; k++) wprev[k] = wcur[k];
                }
            }

            // quad combine over c-quarters (lanes q=0..3 consecutive in warp)
#pragma unroll
            for (int p = 0; p < 8; p++) {
                acc0[p] += __shfl_xor_sync(0xffffffffu, acc0[p], 1);
                acc0[p] += __shfl_xor_sync(0xffffffffu, acc0[p], 2);
                acc1[p] += __shfl_xor_sync(0xffffffffu, acc1[p], 1);
                acc1[p] += __shfl_xor_sync(0xffffffffu, acc1[p], 2);
            }

            if (q == 0) {
                float* op = g_s2 + ((b * 50 + oc) * 8 + ph0) * 8;
                float lsum = 0.f, lsq = 0.f;
#pragma unroll
                for (int p = 0; p < 8; p++) {
                    op[p] = acc0[p];
                    lsum += acc0[p];
                    lsq  += acc0[p] * acc0[p];
                }
#pragma unroll
                for (int p = 0; p < 8; p++) {
                    op[8 + p] = acc1[p];
                    lsum += acc1[p];
                    lsq  += acc1[p] * acc1[p];
                }
                sm.b.red_s[oc * 4 + phpair] = lsum;
                sm.b.red_q[oc * 4 + phpair] = lsq;
            }
        }
        __syncthreads();

        if (tid < 50) {   // per-oc reduce over 4 ph-pairs (deterministic)
            float s = 0.f, q = 0.f;
            for (int t = 0; t < 4; t++) { s += sm.b.red_s[tid * 4 + t]; q += sm.b.red_q[tid * 4 + t]; }
            g_bsum2[tid * 128 + b] = s;
            g_bsq2[tid * 128 + b]  = q;
        }
    }

    grid_barrier();

    // ======================= STAGE C: bn2+pool + fc1 ========================
    {
        const int bg = blk >> 2;
        const int oq = blk & 3;
        const int b0 = bg * 4;

        // bnparam2: 32 warps cover 50 channels (redundant per block)
        for (int c = wid; c < 50; c += 32) {
            float s = 0.f, q = 0.f;
#pragma unroll
            for (int i = 0; i < 4; i++) {
                const int bb = lane + 32 * i;
                s += g_bsum2[c * 128 + bb];
                q += g_bsq2[c * 128 + bb];
            }
#pragma unroll
            for (int d = 16; d; d >>= 1) {
                s += __shfl_xor_sync(0xffffffffu, s, d);
                q += __shfl_xor_sync(0xffffffffu, q, d);
            }
            if (lane == 0) {
                const float invN = 1.f / (128.f * 8.f * 8.f);
                float m = s * invN;
                float v = q * invN - m * m;
                float sc = gamma2[c] * rsqrtf(v + 1e-5f);
                sm.c.s2s[c] = sc;
                sm.c.s2b[c] = beta2[c] - m * sc;
            }
        }
        __syncthreads();

        for (int i = tid; i < 3200; i += 1024) {
            const int bb = i / 800;
            const int o  = i % 800;
            const int c   = o / 16;
            const int r   = (o % 16) / 4;
            const int col = o % 4;
            const float* base = g_s2 + (((b0 + bb) * 50 + c) * 8 + r * 2) * 8 + col * 2;
            const float s = sm.c.s2s[c], be = sm.c.s2b[c];
            float a0 = base[0] * s + be;
            float a1 = base[1] * s + be;
            float a2 = base[8] * s + be;
            float a3 = base[9] * s + be;
            sm.c.p_s[bb][o] = fmaxf(fmaxf(a0, a1), fmaxf(a2, a3));
        }
        __syncthreads();

        // 32 warps x 4 outputs x 4 batches
        int olist[4];
        const float4* wrow[4];
#pragma unroll
        for (int j = 0; j < 4; j++) {
            int idx = wid * 4 + j;
            bool valid = idx < 125;
            int o = oq * 125 + (valid ? idx : 0);
            olist[j] = valid ? o : -1;
            wrow[j] = (const float4*)(fc1_w + o * 800);
        }

        float acc[4][4];
#pragma unroll
        for (int j = 0; j < 4; j++)
#pragma unroll
            for (int bb = 0; bb < 4; bb++) acc[j][bb] = 0.f;

#pragma unroll
        for (int i = 0; i < 7; i++) {
            const int fidx = lane + 32 * i;
            const bool v = fidx < 200;
            float4 x4[4];
#pragma unroll
            for (int bb = 0; bb < 4; bb++)
                x4[bb] = v ? ((const float4*)sm.c.p_s[bb])[fidx] : make_float4(0.f,0.f,0.f,0.f);
#pragma unroll
            for (int j = 0; j < 4; j++) {
                float4 wv = v ? wrow[j][fidx] : make_float4(0.f,0.f,0.f,0.f);
#pragma unroll
                for (int bb = 0; bb < 4; bb++) {
                    acc[j][bb] = fmaf(wv.x, x4[bb].x, acc[j][bb]);
                    acc[j][bb] = fmaf(wv.y, x4[bb].y, acc[j][bb]);
                    acc[j][bb] = fmaf(wv.z, x4[bb].z, acc[j][bb]);
                    acc[j][bb] = fmaf(wv.w, x4[bb].w, acc[j][bb]);
                }
            }
        }

#pragma unroll
        for (int j = 0; j < 4; j++) {
#pragma unroll
            for (int bb = 0; bb < 4; bb++) {
                float a = acc[j][bb];
#pragma unroll
                for (int d = 16; d; d >>= 1) a += __shfl_xor_sync(0xffffffffu, a, d);
                acc[j][bb] = a;
            }
            if (lane == 0 && olist[j] >= 0) {
                const float bia = fc1_b[olist[j]];
#pragma unroll
                for (int bb = 0; bb < 4; bb++)
                    g_h[(b0 + bb) * 500 + olist[j]] = fmaxf(acc[j][bb] + bia, 0.f);
            }
        }
    }

    grid_barrier();

    // ======================= STAGE D: fc2 + softmax =========================
    {
        const int b = blk;
        if (tid < 320) {
            float a = 0.f;
            const float* wr = fc2_w + wid * 500;
            const float* hr = g_h + b * 500;
#pragma unroll
            for (int i = 0; i < 16; i++) {
                int k = lane + 32 * i;
                if (k < 500) a = fmaf(wr[k], hr[k], a);
            }
#pragma unroll
            for (int d = 16; d; d >>= 1) a += __shfl_xor_sync(0xffffffffu, a, d);
            if (lane == 0) sm.d.logits[wid] = a + fc2_b[wid];
        }
        __syncthreads();

        if (tid < 10) {
            const int j = tid;
            float mx = -1e30f;
            for (int t = 0; t < 10; t++) mx = fmaxf(mx, sm.d.logits[t]);
            float sum = 0.f;
            for (int t = 0; t < 10; t++) sum += expf(sm.d.logits[t] - mx);
            out[b * 10 + j] = expf(sm.d.logits[j] - mx) / sum;
        }
    }
}

// ---------------- launch ----------------------------------------------------
extern "C" void kernel_launch(void* const* d_in, const int* in_sizes, int n_in,
                              void* d_out, int out_size) {
    const float* x      = (const float*)d_in[0];
    const float* w1     = (const float*)d_in[1];
    const float* gamma1 = (const float*)d_in[2];
    const float* beta1  = (const float*)d_in[3];
    const float* w2     = (const float*)d_in[4];
    const float* gamma2 = (const float*)d_in[5];
    const float* beta2  = (const float*)d_in[6];
    const float* fc1_w  = (const float*)d_in[7];
    const float* fc1_b  = (const float*)d_in[8];
    const float* fc2_w  = (const float*)d_in[9];
    const float* fc2_b  = (const float*)d_in[10];
    float* out = (float*)d_out;

    mega_k<<<128, 1024>>>(x, w1, gamma1, beta1, w2, gamma2, beta2,
                          fc1_w, fc1_b, fc2_w, fc2_b, out);
}

// round 13
// speedup vs baseline: 1.4039x; 1.0790x over previous
#include <cuda_runtime.h>
#include <math.h>

typedef unsigned long long u64;

// ---------------- scratch (device globals; no allocation allowed) ----------
__device__ float g_h[128 * 500];             // fc1 activations
__device__ __align__(16) float g_w2k[50 * 20 * 5 * 8];  // w2 [oc][c][kh][8] (pad 5->8)
__device__ __align__(16) float g_s2mm[128 * 50 * 4 * 8]; // s2 window [b][oc][prow][max4|min4]

__device__ float g_bsum1[20 * 128], g_bsq1[20 * 128];
__device__ float g_bsum2[50 * 128], g_bsq2[50 * 128];

__device__ u64 g_barctr = 0;  // monotonic epoch barrier counter

// grid-wide barrier: monotonic counter, safe across graph replays
__device__ __forceinline__ void grid_barrier() {
    __syncthreads();
    if (threadIdx.x == 0) {
        __threadfence();
        u64 old = atomicAdd(&g_barctr, 1ULL);
        u64 target = (old / gridDim.x + 1ULL) * (u64)gridDim.x;
        while (*((volatile u64*)&g_barctr) < target) { }
        __threadfence();
    }
    __syncthreads();
}

// ---------------- shared memory layout ---------------------------------------
struct AB {
    float pmax[2880];   // pooled-window max of conv1 [c][prow][pcol], survives A->B
    float pmin[2880];   // pooled-window min
    union {
        struct { float xs[784]; float ws[500]; float red_s[960]; float red_q[960]; } a;
        struct { float s1s[20]; float s1b[20]; float red_s[200]; float red_q[200]; } b;
    } u;
};
struct SC { float p_s[8][800]; float s2s[50]; float s2b[50]; };
struct SD { float logits[10]; };
union SU { AB ab; SC c; SD d; };

// ---------------- mega kernel ----------------------------------------------
__global__ __launch_bounds__(1024, 1) void mega_k(
    const float* __restrict__ x,      const float* __restrict__ w1,
    const float* __restrict__ gamma1, const float* __restrict__ beta1,
    const float* __restrict__ w2,
    const float* __restrict__ gamma2, const float* __restrict__ beta2,
    const float* __restrict__ fc1_w,  const float* __restrict__ fc1_b,
    const float* __restrict__ fc2_w,  const float* __restrict__ fc2_b,
    float* __restrict__ out)
{
    __shared__ __align__(16) SU sm;

    const int blk  = blockIdx.x;        // 0..127
    const int tid  = threadIdx.x;
    const int wid  = tid / 32;
    const int lane = tid % 32;

    // ======================= STAGE A: adder1 (+ w2 repack) =================
    // thread = (oc 0..19, half 0..1, ph 0..23); conv out stays in registers,
    // pooled window max/min -> persistent smem. No global conv1 output.
    {
        const int b = blk;
        // w2 repack slice -> kh-major padded layout: 128 blocks x 196 >= 25000
        {
            const int i = b * 196 + tid;
            if (tid < 196 && i < 25000) {
                const int oc = i / 500;
                const int r  = i % 500;
                const int c  = r / 25;
                const int k  = r % 25;
                g_w2k[(((oc * 20 + c) * 5 + (k / 5)) * 8) + (k % 5)] = w2[i];
            }
        }
        for (int i = tid; i < 784; i += 1024) sm.ab.u.a.xs[i] = x[b * 784 + i];
        for (int i = tid; i < 500; i += 1024) sm.ab.u.a.ws[i] = w1[i];
        __syncthreads();

        if (tid < 960) {
            const int oc   = tid / 48;
            const int r    = tid % 48;
            const int half = r / 24;          // pw block: half*12 .. half*12+11
            const int ph   = r % 24;          // (ph, ph^1) pairs on adjacent lanes

            float acc[12];
#pragma unroll
            for (int p = 0; p < 12; p++) acc[p] = 0.f;

#pragma unroll
            for (int kh = 0; kh < 5; kh++) {
                const float4* xrow = (const float4*)(sm.ab.u.a.xs + (ph + kh) * 28 + half * 12);
                float xr[16];
                float4 v0 = xrow[0], v1 = xrow[1], v2 = xrow[2], v3 = xrow[3];
                xr[0]=v0.x; xr[1]=v0.y; xr[2]=v0.z; xr[3]=v0.w;
                xr[4]=v1.x; xr[5]=v1.y; xr[6]=v1.z; xr[7]=v1.w;
                xr[8]=v2.x; xr[9]=v2.y; xr[10]=v2.z; xr[11]=v2.w;
                xr[12]=v3.x; xr[13]=v3.y; xr[14]=v3.z; xr[15]=v3.w;
#pragma unroll
                for (int kw = 0; kw < 5; kw++) {
                    const float w = sm.ab.u.a.ws[oc * 25 + kh * 5 + kw];
#pragma unroll
                    for (int p = 0; p < 12; p++) {
                        float d = fmaf(w, -1.0f, xr[p + kw]);          // FFMA-imm rt1
                        acc[p]  = fmaf(fabsf(d), -1.0f, acc[p]);       // FFMA-imm rt1
                    }
                }
            }

            // BN partials on raw values
            float lsum = 0.f, lsq = 0.f;
#pragma unroll
            for (int p = 0; p < 12; p++) { lsum += acc[p]; lsq += acc[p] * acc[p]; }
            sm.ab.u.a.red_s[tid] = lsum;
            sm.ab.u.a.red_q[tid] = lsq;

            // column-pair max/min, then row-pair via shuffle with lane+1
            float cmx[6], cmn[6];
#pragma unroll
            for (int j = 0; j < 6; j++) {
                cmx[j] = fmaxf(acc[2*j], acc[2*j+1]);
                cmn[j] = fminf(acc[2*j], acc[2*j+1]);
            }
#pragma unroll
            for (int j = 0; j < 6; j++) {
                float omx = __shfl_down_sync(0xffffffffu, cmx[j], 1);
                float omn = __shfl_down_sync(0xffffffffu, cmn[j], 1);
                cmx[j] = fmaxf(cmx[j], omx);
                cmn[j] = fminf(cmn[j], omn);
            }
            if ((ph & 1) == 0) {
                const int prow = ph >> 1;
                const int base = oc * 144 + prow * 12 + half * 6;
#pragma unroll
                for (int j = 0; j < 6; j++) {
                    sm.ab.pmax[base + j] = cmx[j];
                    sm.ab.pmin[base + j] = cmn[j];
                }
            }
        }
        __syncthreads();

        if (tid < 960 && (tid % 48) == 0) {   // 20 threads, deterministic
            const int oc = tid / 48;
            float s = 0.f, q = 0.f;
            for (int t = 0; t < 48; t++) { s += sm.ab.u.a.red_s[oc * 48 + t]; q += sm.ab.u.a.red_q[oc * 48 + t]; }
            g_bsum1[oc * 128 + b] = s;
            g_bsq1[oc * 128 + b]  = q;
        }
    }

    grid_barrier();

    // ======================= STAGE B: bn1+pool (in smem) + adder2 ==========
    // thread = (oc 0..49, phpair 0..3, cquarter 0..3): 2 output rows, 5 channels
    {
        const int b = blk;

        // bnparam1: warp per channel (redundant per block, deterministic)
        if (wid < 20) {
            float s = 0.f, q = 0.f;
#pragma unroll
            for (int i = 0; i < 4; i++) {
                const int bb = lane + 32 * i;
                s += g_bsum1[wid * 128 + bb];
                q += g_bsq1[wid * 128 + bb];
            }
#pragma unroll
            for (int d = 16; d; d >>= 1) {
                s += __shfl_xor_sync(0xffffffffu, s, d);
                q += __shfl_xor_sync(0xffffffffu, q, d);
            }
            if (lane == 0) {
                const float invN = 1.f / (128.f * 24.f * 24.f);
                float m = s * invN;
                float v = q * invN - m * m;
                float sc = gamma1[wid] * rsqrtf(v + 1e-5f);
                sm.ab.u.b.s1s[wid] = sc;
                sm.ab.u.b.s1b[wid] = beta1[wid] - m * sc;
            }
        }
        __syncthreads();

        // bn1 + pool, in place over pmax: pool = max(s*mx+be, s*mn+be)
        for (int i = tid; i < 2880; i += 1024) {
            const int c = i / 144;
            const float s = sm.ab.u.b.s1s[c], be = sm.ab.u.b.s1b[c];
            float v = fmaxf(fmaf(s, sm.ab.pmax[i], be), fmaf(s, sm.ab.pmin[i], be));
            sm.ab.pmax[i] = v;
        }
        __syncthreads();

        if (tid < 800) {
            const int oc     = tid / 16;
            const int sub    = tid % 16;
            const int phpair = sub >> 2;        // 0..3 -> rows ph0, ph0+1
            const int q      = sub & 3;         // c quarter: q*5 .. q*5+4
            const int ph0    = phpair * 2;

            float acc0[8], acc1[8];
#pragma unroll
            for (int p = 0; p < 8; p++) { acc0[p] = 0.f; acc1[p] = 0.f; }

#pragma unroll
            for (int cc = 0; cc < 5; cc++) {
                const int c = q * 5 + cc;
                const float* xc = sm.ab.pmax + c * 144 + ph0 * 12;
                const float4* wk = (const float4*)(g_w2k + ((oc * 20 + c) * 5) * 8);

                float wprev[5];
#pragma unroll
                for (int r = 0; r < 6; r++) {
                    float wcur[5];
                    if (r < 5) {
                        float4 wa = wk[r * 2];
                        float4 wb = wk[r * 2 + 1];
                        wcur[0] = wa.x; wcur[1] = wa.y; wcur[2] = wa.z;
                        wcur[3] = wa.w; wcur[4] = wb.x;
                    }
                    const float4* xrow = (const float4*)(xc + r * 12);
                    float4 v0 = xrow[0], v1 = xrow[1], v2 = xrow[2];
                    float xr[12];
                    xr[0]=v0.x; xr[1]=v0.y; xr[2]=v0.z; xr[3]=v0.w;
                    xr[4]=v1.x; xr[5]=v1.y; xr[6]=v1.z; xr[7]=v1.w;
                    xr[8]=v2.x; xr[9]=v2.y; xr[10]=v2.z; xr[11]=v2.w;

                    if (r < 5) {   // row0: kh = r
#pragma unroll
                        for (int kw = 0; kw < 5; kw++) {
                            const float w = wcur[kw];
#pragma unroll
                            for (int p = 0; p < 8; p++) {
                                float d = fmaf(w, -1.0f, xr[p + kw]);
                                acc0[p] = fmaf(fabsf(d), -1.0f, acc0[p]);
                            }
                        }
                    }
                    if (r >= 1) {  // row1: kh = r-1
#pragma unroll
                        for (int kw = 0; kw < 5; kw++) {
                            const float w = wprev[kw];
#pragma unroll
                            for (int p = 0; p < 8; p++) {
                                float d = fmaf(w, -1.0f, xr[p + kw]);
                                acc1[p] = fmaf(fabsf(d), -1.0f, acc1[p]);
                            }
                        }
                    }
#pragma unroll
                    for (int k = 0; k < 5; k++) wprev[k] = wcur[k];
                }
            }

            // quad combine over c-quarters (lanes q=0..3 consecutive in warp)
#pragma unroll
            for (int p = 0; p < 8; p++) {
                acc0[p] += __shfl_xor_sync(0xffffffffu, acc0[p], 1);
                acc0[p] += __shfl_xor_sync(0xffffffffu, acc0[p], 2);
                acc1[p] += __shfl_xor_sync(0xffffffffu, acc1[p], 1);
                acc1[p] += __shfl_xor_sync(0xffffffffu, acc1[p], 2);
            }

            if (q == 0) {
                // BN partials on raw values
                float lsum = 0.f, lsq = 0.f;
#pragma unroll
                for (int p = 0; p < 8; p++) {
                    lsum += acc0[p]; lsq += acc0[p] * acc0[p];
                }
#pragma unroll
                for (int p = 0; p < 8; p++) {
                    lsum += acc1[p]; lsq += acc1[p] * acc1[p];
                }
                sm.ab.u.b.red_s[oc * 4 + phpair] = lsum;
                sm.ab.u.b.red_q[oc * 4 + phpair] = lsq;

                // 2x2 window max/min (both rows live in this thread)
                float wmx[4], wmn[4];
#pragma unroll
                for (int j = 0; j < 4; j++) {
                    float m0x = fmaxf(acc0[2*j], acc0[2*j+1]);
                    float m1x = fmaxf(acc1[2*j], acc1[2*j+1]);
                    float m0n = fminf(acc0[2*j], acc0[2*j+1]);
                    float m1n = fminf(acc1[2*j], acc1[2*j+1]);
                    wmx[j] = fmaxf(m0x, m1x);
                    wmn[j] = fminf(m0n, m1n);
                }
                float4* op = (float4*)(g_s2mm + ((b * 50 + oc) * 4 + phpair) * 8);
                op[0] = make_float4(wmx[0], wmx[1], wmx[2], wmx[3]);
                op[1] = make_float4(wmn[0], wmn[1], wmn[2], wmn[3]);
            }
        }
        __syncthreads();

        if (tid < 50) {   // per-oc reduce over 4 ph-pairs (deterministic)
            float s = 0.f, q = 0.f;
            for (int t = 0; t < 4; t++) { s += sm.ab.u.b.red_s[tid * 4 + t]; q += sm.ab.u.b.red_q[tid * 4 + t]; }
            g_bsum2[tid * 128 + b] = s;
            g_bsq2[tid * 128 + b]  = q;
        }
    }

    grid_barrier();

    // ======================= STAGE C: bn2+pool + fc1 ========================
    // grid = 16 batch-groups (8 batches) x 8 output slices
    {
        const int bg = blk >> 3;             // 0..15
        const int oq = blk & 7;              // 0..7
        const int b0 = bg * 8;
        const int off   = (oq < 4) ? oq * 63 : 252 + (oq - 4) * 62;
        const int width = (oq < 4) ? 63 : 62;

        // bnparam2: 32 warps cover 50 channels (redundant per block)
        for (int c = wid; c < 50; c += 32) {
            float s = 0.f, q = 0.f;
#pragma unroll
            for (int i = 0; i < 4; i++) {
                const int bb = lane + 32 * i;
                s += g_bsum2[c * 128 + bb];
                q += g_bsq2[c * 128 + bb];
            }
#pragma unroll
            for (int d = 16; d; d >>= 1) {
                s += __shfl_xor_sync(0xffffffffu, s, d);
                q += __shfl_xor_sync(0xffffffffu, q, d);
            }
            if (lane == 0) {
                const float invN = 1.f / (128.f * 8.f * 8.f);
                float m = s * invN;
                float v = q * invN - m * m;
                float sc = gamma2[c] * rsqrtf(v + 1e-5f);
                sm.c.s2s[c] = sc;
                sm.c.s2b[c] = beta2[c] - m * sc;
            }
        }
        __syncthreads();

        // bn2 + pool from window max/min: 8 batches x 800
        for (int i = tid; i < 6400; i += 1024) {
            const int bb = i / 800;
            const int o  = i % 800;
            const int c   = o / 16;
            const int r   = (o % 16) / 4;
            const int col = o % 4;
            const float* wp = g_s2mm + (((b0 + bb) * 50 + c) * 4 + r) * 8;
            const float s = sm.c.s2s[c], be = sm.c.s2b[c];
            sm.c.p_s[bb][o] = fmaxf(fmaf(s, wp[col], be), fmaf(s, wp[4 + col], be));
        }
        __syncthreads();

        // warp handles 2 outputs x 8 batches; x streamed per batch
        const int i0 = wid * 2;
        const bool v0 = (i0 < width), v1 = (i0 + 1 < width);
        const int o0 = off + (v0 ? i0 : 0);
        const int o1 = off + (v1 ? i0 + 1 : 0);
        const float4* wr0 = (const float4*)(fc1_w + o0 * 800);
        const float4* wr1 = (const float4*)(fc1_w + o1 * 800);

        float acc[2][8];
#pragma unroll
        for (int j = 0; j < 2; j++)
#pragma unroll
            for (int bb = 0; bb < 8; bb++) acc[j][bb] = 0.f;

#pragma unroll
        for (int i = 0; i < 7; i++) {
            const int fidx = lane + 32 * i;
            if (fidx < 200) {
                float4 wv0 = wr0[fidx];
                float4 wv1 = wr1[fidx];
#pragma unroll
                for (int bb = 0; bb < 8; bb++) {
                    float4 xv = ((const float4*)sm.c.p_s[bb])[fidx];
                    acc[0][bb] = fmaf(wv0.x, xv.x, acc[0][bb]);
                    acc[0][bb] = fmaf(wv0.y, xv.y, acc[0][bb]);
                    acc[0][bb] = fmaf(wv0.z, xv.z, acc[0][bb]);
                    acc[0][bb] = fmaf(wv0.w, xv.w, acc[0][bb]);
                    acc[1][bb] = fmaf(wv1.x, xv.x, acc[1][bb]);
                    acc[1][bb] = fmaf(wv1.y, xv.y, acc[1][bb]);
                    acc[1][bb] = fmaf(wv1.z, xv.z, acc[1][bb]);
                    acc[1][bb] = fmaf(wv1.w, xv.w, acc[1][bb]);
                }
            }
        }

#pragma unroll
        for (int j = 0; j < 2; j++) {
#pragma unroll
            for (int bb = 0; bb < 8; bb++) {
                float a = acc[j][bb];
#pragma unroll
                for (int d = 16; d; d >>= 1) a += __shfl_xor_sync(0xffffffffu, a, d);
                acc[j][bb] = a;
            }
        }
        if (lane == 0) {
            if (v0) {
                const float bia = fc1_b[o0];
#pragma unroll
                for (int bb = 0; bb < 8; bb++)
                    g_h[(b0 + bb) * 500 + o0] = fmaxf(acc[0][bb] + bia, 0.f);
            }
            if (v1) {
                const float bia = fc1_b[o1];
#pragma unroll
                for (int bb = 0; bb < 8; bb++)
                    g_h[(b0 + bb) * 500 + o1] = fmaxf(acc[1][bb] + bia, 0.f);
            }
        }
    }

    grid_barrier();

    // ======================= STAGE D: fc2 + softmax =========================
    {
        const int b = blk;
        if (tid < 320) {
            float a = 0.f;
            const float* wr = fc2_w + wid * 500;
            const float* hr = g_h + b * 500;
#pragma unroll
            for (int i = 0; i < 16; i++) {
                int k = lane + 32 * i;
                if (k < 500) a = fmaf(wr[k], hr[k], a);
            }
#pragma unroll
            for (int d = 16; d; d >>= 1) a += __shfl_xor_sync(0xffffffffu, a, d);
            if (lane == 0) sm.d.logits[wid] = a + fc2_b[wid];
        }
        __syncthreads();

        if (tid < 10) {
            const int j = tid;
            float mx = -1e30f;
            for (int t = 0; t < 10; t++) mx = fmaxf(mx, sm.d.logits[t]);
            float sum = 0.f;
            for (int t = 0; t < 10; t++) sum += expf(sm.d.logits[t] - mx);
            out[b * 10 + j] = expf(sm.d.logits[j] - mx) / sum;
        }
    }
}

// ---------------- launch ----------------------------------------------------
extern "C" void kernel_launch(void* const* d_in, const int* in_sizes, int n_in,
                              void* d_out, int out_size) {
    const float* x      = (const float*)d_in[0];
    const float* w1     = (const float*)d_in[1];
    const float* gamma1 = (const float*)d_in[2];
    const float* beta1  = (const float*)d_in[3];
    const float* w2     = (const float*)d_in[4];
    const float* gamma2 = (const float*)d_in[5];
    const float* beta2  = (const float*)d_in[6];
    const float* fc1_w  = (const float*)d_in[7];
    const float* fc1_b  = (const float*)d_in[8];
    const float* fc2_w  = (const float*)d_in[9];
    const float* fc2_b  = (const float*)d_in[10];
    float* out = (float*)d_out;

    mega_k<<<128, 1024>>>(x, w1, gamma1, beta1, w2, gamma2, beta2,
                          fc1_w, fc1_b, fc2_w, fc2_b, out);
}

// round 14
// speedup vs baseline: 1.4246x; 1.0147x over previous
#include <cuda_runtime.h>
#include <math.h>

typedef unsigned long long u64;

// ---------------- scratch (device globals; no allocation allowed) ----------
__device__ float g_h[128 * 500];             // fc1 activations
__device__ __align__(16) float g_w2k[50 * 20 * 5 * 8];  // w2 [oc][c][kh][8] (pad 5->8)
__device__ __align__(16) float g_s2mm[128 * 50 * 4 * 8]; // s2 window [b][oc][prow][max4|min4]

__device__ float g_bsum1[20 * 128], g_bsq1[20 * 128];
__device__ float g_bsum2[50 * 128], g_bsq2[50 * 128];

__device__ u64 g_barctr = 0;  // monotonic epoch barrier counter

// grid-wide barrier: monotonic counter, safe across graph replays
__device__ __forceinline__ void grid_barrier() {
    __syncthreads();
    if (threadIdx.x == 0) {
        __threadfence();
        u64 old = atomicAdd(&g_barctr, 1ULL);
        u64 target = (old / gridDim.x + 1ULL) * (u64)gridDim.x;
        while (*((volatile u64*)&g_barctr) < target) { }
        __threadfence();
    }
    __syncthreads();
}

#define CSTR 148   // padded channel stride (words): 5*CSTR % 32 == 4 -> conflict-free

// ---------------- shared memory layout ---------------------------------------
struct AB {
    float pmax[20 * CSTR];   // pooled-window max of conv1 [c][prow*12+pcol]
    float pmin[20 * CSTR];   // pooled-window min
    union {
        struct { float xs[784]; float ws[500]; float red_s[960]; float red_q[960]; } a;
        struct { float s1s[20]; float s1b[20]; float red_s[200]; float red_q[200]; } b;
    } u;
};
struct SC { float p_s[8][800]; float s2s[50]; float s2b[50]; };
struct SD { float logits[10]; };
union SU { AB ab; SC c; SD d; };

// ---------------- mega kernel ----------------------------------------------
__global__ __launch_bounds__(1024, 1) void mega_k(
    const float* __restrict__ x,      const float* __restrict__ w1,
    const float* __restrict__ gamma1, const float* __restrict__ beta1,
    const float* __restrict__ w2,
    const float* __restrict__ gamma2, const float* __restrict__ beta2,
    const float* __restrict__ fc1_w,  const float* __restrict__ fc1_b,
    const float* __restrict__ fc2_w,  const float* __restrict__ fc2_b,
    float* __restrict__ out)
{
    __shared__ __align__(16) SU sm;

    const int blk  = blockIdx.x;        // 0..127
    const int tid  = threadIdx.x;
    const int wid  = tid / 32;
    const int lane = tid % 32;

    // ======================= STAGE A: adder1 (+ w2 repack) =================
    {
        const int b = blk;
        // w2 repack slice -> kh-major padded layout: 128 blocks x 196 >= 25000
        {
            const int i = b * 196 + tid;
            if (tid < 196 && i < 25000) {
                const int oc = i / 500;
                const int r  = i % 500;
                const int c  = r / 25;
                const int k  = r % 25;
                g_w2k[(((oc * 20 + c) * 5 + (k / 5)) * 8) + (k % 5)] = w2[i];
            }
        }
        for (int i = tid; i < 784; i += 1024) sm.ab.u.a.xs[i] = x[b * 784 + i];
        for (int i = tid; i < 500; i += 1024) sm.ab.u.a.ws[i] = w1[i];
        __syncthreads();

        if (tid < 960) {
            const int oc   = tid / 48;
            const int r    = tid % 48;
            const int half = r / 24;          // pw block: half*12 .. half*12+11
            const int ph   = r % 24;          // (ph, ph^1) pairs on adjacent lanes

            float acc[12];
#pragma unroll
            for (int p = 0; p < 12; p++) acc[p] = 0.f;

#pragma unroll
            for (int kh = 0; kh < 5; kh++) {
                const float4* xrow = (const float4*)(sm.ab.u.a.xs + (ph + kh) * 28 + half * 12);
                float xr[16];
                float4 v0 = xrow[0], v1 = xrow[1], v2 = xrow[2], v3 = xrow[3];
                xr[0]=v0.x; xr[1]=v0.y; xr[2]=v0.z; xr[3]=v0.w;
                xr[4]=v1.x; xr[5]=v1.y; xr[6]=v1.z; xr[7]=v1.w;
                xr[8]=v2.x; xr[9]=v2.y; xr[10]=v2.z; xr[11]=v2.w;
                xr[12]=v3.x; xr[13]=v3.y; xr[14]=v3.z; xr[15]=v3.w;
#pragma unroll
                for (int kw = 0; kw < 5; kw++) {
                    const float w = sm.ab.u.a.ws[oc * 25 + kh * 5 + kw];
#pragma unroll
                    for (int p = 0; p < 12; p++) {
                        float d = fmaf(w, -1.0f, xr[p + kw]);          // FFMA-imm rt1
                        acc[p]  = fmaf(fabsf(d), -1.0f, acc[p]);       // FFMA-imm rt1
                    }
                }
            }

            // BN partials on raw values
            float lsum = 0.f, lsq = 0.f;
#pragma unroll
            for (int p = 0; p < 12; p++) { lsum += acc[p]; lsq += acc[p] * acc[p]; }
            sm.ab.u.a.red_s[tid] = lsum;
            sm.ab.u.a.red_q[tid] = lsq;

            // column-pair max/min, then row-pair via shuffle with lane+1
            float cmx[6], cmn[6];
#pragma unroll
            for (int j = 0; j < 6; j++) {
                cmx[j] = fmaxf(acc[2*j], acc[2*j+1]);
                cmn[j] = fminf(acc[2*j], acc[2*j+1]);
            }
#pragma unroll
            for (int j = 0; j < 6; j++) {
                float omx = __shfl_down_sync(0xffffffffu, cmx[j], 1);
                float omn = __shfl_down_sync(0xffffffffu, cmn[j], 1);
                cmx[j] = fmaxf(cmx[j], omx);
                cmn[j] = fminf(cmn[j], omn);
            }
            if ((ph & 1) == 0) {
                const int prow = ph >> 1;
                const int base = oc * CSTR + prow * 12 + half * 6;
#pragma unroll
                for (int j = 0; j < 6; j++) {
                    sm.ab.pmax[base + j] = cmx[j];
                    sm.ab.pmin[base + j] = cmn[j];
                }
            }
        }
        __syncthreads();

        if (tid < 960 && (tid % 48) == 0) {   // 20 threads, deterministic
            const int oc = tid / 48;
            float s = 0.f, q = 0.f;
            for (int t = 0; t < 48; t++) { s += sm.ab.u.a.red_s[oc * 48 + t]; q += sm.ab.u.a.red_q[oc * 48 + t]; }
            g_bsum1[oc * 128 + b] = s;
            g_bsq1[oc * 128 + b]  = q;
        }
    }

    grid_barrier();

    // ======================= STAGE B: bn1+pool (in smem) + adder2 ==========
    // thread = (oc 0..49, sub = cquarter*4 + phpair): 2 output rows, 5 channels
    {
        const int b = blk;

        // bnparam1: warp per channel (redundant per block, deterministic)
        if (wid < 20) {
            float s = 0.f, q = 0.f;
#pragma unroll
            for (int i = 0; i < 4; i++) {
                const int bb = lane + 32 * i;
                s += g_bsum1[wid * 128 + bb];
                q += g_bsq1[wid * 128 + bb];
            }
#pragma unroll
            for (int d = 16; d; d >>= 1) {
                s += __shfl_xor_sync(0xffffffffu, s, d);
                q += __shfl_xor_sync(0xffffffffu, q, d);
            }
            if (lane == 0) {
                const float invN = 1.f / (128.f * 24.f * 24.f);
                float m = s * invN;
                float v = q * invN - m * m;
                float sc = gamma1[wid] * rsqrtf(v + 1e-5f);
                sm.ab.u.b.s1s[wid] = sc;
                sm.ab.u.b.s1b[wid] = beta1[wid] - m * sc;
            }
        }
        __syncthreads();

        // bn1 + pool, in place over pmax: pool = max(s*mx+be, s*mn+be)
        for (int i = tid; i < 20 * CSTR; i += 1024) {
            const int c   = i / CSTR;
            const int rem = i % CSTR;
            if (rem < 144) {
                const float s = sm.ab.u.b.s1s[c], be = sm.ab.u.b.s1b[c];
                float v = fmaxf(fmaf(s, sm.ab.pmax[i], be), fmaf(s, sm.ab.pmin[i], be));
                sm.ab.pmax[i] = v;
            }
        }
        __syncthreads();

        if (tid < 800) {
            const int oc     = tid / 16;
            const int sub    = tid % 16;
            const int q      = sub >> 2;        // c quarter: q*5 .. q*5+4
            const int phpair = sub & 3;         // rows ph0, ph0+1
            const int ph0    = phpair * 2;

            float acc0[8], acc1[8];
#pragma unroll
            for (int p = 0; p < 8; p++) { acc0[p] = 0.f; acc1[p] = 0.f; }

#pragma unroll
            for (int cc = 0; cc < 5; cc++) {
                const int c = q * 5 + cc;
                const float* xc = sm.ab.pmax + c * CSTR + ph0 * 12;
                const float4* wk = (const float4*)(g_w2k + ((oc * 20 + c) * 5) * 8);

                float wprev[5];
#pragma unroll
                for (int r = 0; r < 6; r++) {
                    float wcur[5];
                    if (r < 5) {
                        float4 wa = wk[r * 2];
                        float4 wb = wk[r * 2 + 1];
                        wcur[0] = wa.x; wcur[1] = wa.y; wcur[2] = wa.z;
                        wcur[3] = wa.w; wcur[4] = wb.x;
                    }
                    const float4* xrow = (const float4*)(xc + r * 12);
                    float4 v0 = xrow[0], v1 = xrow[1], v2 = xrow[2];
                    float xr[12];
                    xr[0]=v0.x; xr[1]=v0.y; xr[2]=v0.z; xr[3]=v0.w;
                    xr[4]=v1.x; xr[5]=v1.y; xr[6]=v1.z; xr[7]=v1.w;
                    xr[8]=v2.x; xr[9]=v2.y; xr[10]=v2.z; xr[11]=v2.w;

                    if (r < 5) {   // row0: kh = r
#pragma unroll
                        for (int kw = 0; kw < 5; kw++) {
                            const float w = wcur[kw];
#pragma unroll
                            for (int p = 0; p < 8; p++) {
                                float d = fmaf(w, -1.0f, xr[p + kw]);
                                acc0[p] = fmaf(fabsf(d), -1.0f, acc0[p]);
                            }
                        }
                    }
                    if (r >= 1) {  // row1: kh = r-1
#pragma unroll
                        for (int kw = 0; kw < 5; kw++) {
                            const float w = wprev[kw];
#pragma unroll
                            for (int p = 0; p < 8; p++) {
                                float d = fmaf(w, -1.0f, xr[p + kw]);
                                acc1[p] = fmaf(fabsf(d), -1.0f, acc1[p]);
                            }
                        }
                    }
#pragma unroll
                    for (int k = 0; k < 5; k++) wprev[k] = wcur[k];
                }
            }

            // quad combine over c-quarters (q bits are lane bits 2,3)
#pragma unroll
            for (int p = 0; p < 8; p++) {
                acc0[p] += __shfl_xor_sync(0xffffffffu, acc0[p], 4);
                acc0[p] += __shfl_xor_sync(0xffffffffu, acc0[p], 8);
                acc1[p] += __shfl_xor_sync(0xffffffffu, acc1[p], 4);
                acc1[p] += __shfl_xor_sync(0xffffffffu, acc1[p], 8);
            }

            if (q == 0) {
                // BN partials on raw values
                float lsum = 0.f, lsq = 0.f;
#pragma unroll
                for (int p = 0; p < 8; p++) {
                    lsum += acc0[p]; lsq += acc0[p] * acc0[p];
                }
#pragma unroll
                for (int p = 0; p < 8; p++) {
                    lsum += acc1[p]; lsq += acc1[p] * acc1[p];
                }
                sm.ab.u.b.red_s[oc * 4 + phpair] = lsum;
                sm.ab.u.b.red_q[oc * 4 + phpair] = lsq;

                // 2x2 window max/min (both rows live in this thread)
                float wmx[4], wmn[4];
#pragma unroll
                for (int j = 0; j < 4; j++) {
                    float m0x = fmaxf(acc0[2*j], acc0[2*j+1]);
                    float m1x = fmaxf(acc1[2*j], acc1[2*j+1]);
                    float m0n = fminf(acc0[2*j], acc0[2*j+1]);
                    float m1n = fminf(acc1[2*j], acc1[2*j+1]);
                    wmx[j] = fmaxf(m0x, m1x);
                    wmn[j] = fminf(m0n, m1n);
                }
                float4* op = (float4*)(g_s2mm + ((b * 50 + oc) * 4 + phpair) * 8);
                op[0] = make_float4(wmx[0], wmx[1], wmx[2], wmx[3]);
                op[1] = make_float4(wmn[0], wmn[1], wmn[2], wmn[3]);
            }
        }
        __syncthreads();

        if (tid < 50) {   // per-oc reduce over 4 ph-pairs (deterministic)
            float s = 0.f, q = 0.f;
            for (int t = 0; t < 4; t++) { s += sm.ab.u.b.red_s[tid * 4 + t]; q += sm.ab.u.b.red_q[tid * 4 + t]; }
            g_bsum2[tid * 128 + b] = s;
            g_bsq2[tid * 128 + b]  = q;
        }
    }

    grid_barrier();

    // ======================= STAGE C: bn2+pool + fc1 ========================
    // grid = 16 batch-groups (8 batches) x 8 output slices
    {
        const int bg = blk >> 3;             // 0..15
        const int oq = blk & 7;              // 0..7
        const int b0 = bg * 8;
        const int off   = (oq < 4) ? oq * 63 : 252 + (oq - 4) * 62;
        const int width = (oq < 4) ? 63 : 62;

        // bnparam2: 32 warps cover 50 channels (redundant per block)
        for (int c = wid; c < 50; c += 32) {
            float s = 0.f, q = 0.f;
#pragma unroll
            for (int i = 0; i < 4; i++) {
                const int bb = lane + 32 * i;
                s += g_bsum2[c * 128 + bb];
                q += g_bsq2[c * 128 + bb];
            }
#pragma unroll
            for (int d = 16; d; d >>= 1) {
                s += __shfl_xor_sync(0xffffffffu, s, d);
                q += __shfl_xor_sync(0xffffffffu, q, d);
            }
            if (lane == 0) {
                const float invN = 1.f / (128.f * 8.f * 8.f);
                float m = s * invN;
                float v = q * invN - m * m;
                float sc = gamma2[c] * rsqrtf(v + 1e-5f);
                sm.c.s2s[c] = sc;
                sm.c.s2b[c] = beta2[c] - m * sc;
            }
        }
        __syncthreads();

        // bn2 + pool from window max/min: 8 batches x 800
        for (int i = tid; i < 6400; i += 1024) {
            const int bb = i / 800;
            const int o  = i % 800;
            const int c   = o / 16;
            const int r   = (o % 16) / 4;
            const int col = o % 4;
            const float* wp = g_s2mm + (((b0 + bb) * 50 + c) * 4 + r) * 8;
            const float s = sm.c.s2s[c], be = sm.c.s2b[c];
            sm.c.p_s[bb][o] = fmaxf(fmaf(s, wp[col], be), fmaf(s, wp[4 + col], be));
        }
        __syncthreads();

        // warp handles 2 outputs x 8 batches; x streamed per batch
        const int i0 = wid * 2;
        const bool v0 = (i0 < width), v1 = (i0 + 1 < width);
        const int o0 = off + (v0 ? i0 : 0);
        const int o1 = off + (v1 ? i0 + 1 : 0);
        const float4* wr0 = (const float4*)(fc1_w + o0 * 800);
        const float4* wr1 = (const float4*)(fc1_w + o1 * 800);

        float acc[2][8];
#pragma unroll
        for (int j = 0; j < 2; j++)
#pragma unroll
            for (int bb = 0; bb < 8; bb++) acc[j][bb] = 0.f;

#pragma unroll
        for (int i = 0; i < 7; i++) {
            const int fidx = lane + 32 * i;
            if (fidx < 200) {
                float4 wv0 = wr0[fidx];
                float4 wv1 = wr1[fidx];
#pragma unroll
                for (int bb = 0; bb < 8; bb++) {
                    float4 xv = ((const float4*)sm.c.p_s[bb])[fidx];
                    acc[0][bb] = fmaf(wv0.x, xv.x, acc[0][bb]);
                    acc[0][bb] = fmaf(wv0.y, xv.y, acc[0][bb]);
                    acc[0][bb] = fmaf(wv0.z, xv.z, acc[0][bb]);
                    acc[0][bb] = fmaf(wv0.w, xv.w, acc[0][bb]);
                    acc[1][bb] = fmaf(wv1.x, xv.x, acc[1][bb]);
                    acc[1][bb] = fmaf(wv1.y, xv.y, acc[1][bb]);
                    acc[1][bb] = fmaf(wv1.z, xv.z, acc[1][bb]);
                    acc[1][bb] = fmaf(wv1.w, xv.w, acc[1][bb]);
                }
            }
        }

#pragma unroll
        for (int j = 0; j < 2; j++) {
#pragma unroll
            for (int bb = 0; bb < 8; bb++) {
                float a = acc[j][bb];
#pragma unroll
                for (int d = 16; d; d >>= 1) a += __shfl_xor_sync(0xffffffffu, a, d);
                acc[j][bb] = a;
            }
        }
        if (lane == 0) {
            if (v0) {
                const float bia = fc1_b[o0];
#pragma unroll
                for (int bb = 0; bb < 8; bb++)
                    g_h[(b0 + bb) * 500 + o0] = fmaxf(acc[0][bb] + bia, 0.f);
            }
            if (v1) {
                const float bia = fc1_b[o1];
#pragma unroll
                for (int bb = 0; bb < 8; bb++)
                    g_h[(b0 + bb) * 500 + o1] = fmaxf(acc[1][bb] + bia, 0.f);
            }
        }
    }

    grid_barrier();

    // ======================= STAGE D: fc2 + softmax =========================
    {
        const int b = blk;
        if (tid < 320) {
            float a = 0.f;
            const float* wr = fc2_w + wid * 500;
            const float* hr = g_h + b * 500;
#pragma unroll
            for (int i = 0; i < 16; i++) {
                int k = lane + 32 * i;
                if (k < 500) a = fmaf(wr[k], hr[k], a);
            }
#pragma unroll
            for (int d = 16; d; d >>= 1) a += __shfl_xor_sync(0xffffffffu, a, d);
            if (lane == 0) sm.d.logits[wid] = a + fc2_b[wid];
        }
        __syncthreads();

        if (tid < 10) {
            const int j = tid;
            float mx = -1e30f;
            for (int t = 0; t < 10; t++) mx = fmaxf(mx, sm.d.logits[t]);
            float sum = 0.f;
            for (int t = 0; t < 10; t++) sum += expf(sm.d.logits[t] - mx);
            out[b * 10 + j] = expf(sm.d.logits[j] - mx) / sum;
        }
    }
}

// ---------------- launch ----------------------------------------------------
extern "C" void kernel_launch(void* const* d_in, const int* in_sizes, int n_in,
                              void* d_out, int out_size) {
    const float* x      = (const float*)d_in[0];
    const float* w1     = (const float*)d_in[1];
    const float* gamma1 = (const float*)d_in[2];
    const float* beta1  = (const float*)d_in[3];
    const float* w2     = (const float*)d_in[4];
    const float* gamma2 = (const float*)d_in[5];
    const float* beta2  = (const float*)d_in[6];
    const float* fc1_w  = (const float*)d_in[7];
    const float* fc1_b  = (const float*)d_in[8];
    const float* fc2_w  = (const float*)d_in[9];
    const float* fc2_b  = (const float*)d_in[10];
    float* out = (float*)d_out;

    mega_k<<<128, 1024>>>(x, w1, gamma1, beta1, w2, gamma2, beta2,
                          fc1_w, fc1_b, fc2_w, fc2_b, out);
}